// round 6
// baseline (speedup 1.0000x reference)
#include <cuda_runtime.h>
#include <math.h>

#define B_    32
#define NIN   2312
#define NHID  512
#define NOUT  10
#define T_    350
#define TK    100
#define THETA 10.0f

// refractory IIR constants
#define D_REF 0.36787944117144233f
#define C_REF (-5.43656365691809f)

// psp alpha-kernel IIR constants: eps[k] = (e/10) * k * d^k, d = e^{-0.1}
#define D_SR  0.90483741803595952f    // exp(-0.1)
#define C_E   0.27182818284590452f    // e/10
#define K2C   1.2340980408667956e-05f // C_E * exp(-10)
#define K3C   1.2340980408667956e-03f // 100 * C_E * exp(-10)

// sparse index structures
#define NCH   8
#define CHUNK 289
#define CAPC  96
#define CAP   192                 // dense per-column capacity (mean 115.6, ~7 sigma margin)
#define WSTRIDE 17                // padded W-slice row stride (floats)
#define DUMMYV  (NIN * WSTRIDE)   // prescaled dummy index -> zero row

#define NCOL  (B_ * T_)           // 11200

// shared-memory layout for gather_kernel (float offsets)
#define WS_FLOATS   ((NIN + 1) * WSTRIDE)                 // 39321
#define OT_OFF      WS_FLOATS                             // otile start
#define IST_OFF     (((OT_OFF + 16 * T_) + 3) & ~3)       // 44924, 16B-aligned
#define GATHER_SMEM_FLOATS (IST_OFF + (12 * 192 * 2 + 3) / 4 + 4)

// ------------------------- static device scratch ---------------------------
__device__ unsigned short g_idx[(size_t)NCOL * NCH * CAPC];
__device__ int            g_cnt[(size_t)NCOL * NCH];
__device__ unsigned short g_cidx[(size_t)NCOL * CAP];   // prescaled i*17
__device__ int            g_ccnt[NCOL];
__device__ float g_y1[(size_t)B_ * NHID * T_];
__device__ float g_s1[(size_t)B_ * NHID * T_];
__device__ float g_z2[(size_t)B_ * NOUT * T_];

// ---------------------------------------------------------------------------
// Build per-(b,t,chunk) lists of active input indices (coalesced over t).
// ---------------------------------------------------------------------------
__global__ __launch_bounds__(128) void build_idx_kernel(const float* __restrict__ X) {
    const int t = blockIdx.x * 128 + threadIdx.x;
    const int c = blockIdx.y;
    const int b = blockIdx.z;
    if (t >= T_) return;

    const int col = b * T_ + t;
    unsigned short* dst = g_idx + ((size_t)col * NCH + c) * CAPC;
    const float* __restrict__ xb = X + (size_t)b * NIN * T_ + t;

    int cnt = 0;
    const int i0 = c * CHUNK;
#pragma unroll 4
    for (int i = i0; i < i0 + CHUNK; i++) {
        float v = xb[(size_t)i * T_];
        if (v != 0.0f) {
            if (cnt < CAPC) dst[cnt] = (unsigned short)i;
            cnt++;
        }
    }
    g_cnt[col * NCH + c] = (cnt < CAPC) ? cnt : CAPC;
}

// ---------------------------------------------------------------------------
// Compact chunked lists into one dense, PRESCALED (i*17) list per column.
// ---------------------------------------------------------------------------
__global__ __launch_bounds__(128) void compact_idx_kernel() {
    const int col = blockIdx.x * 128 + threadIdx.x;
    if (col >= NCOL) return;
    unsigned short* dst = g_cidx + (size_t)col * CAP;
    int n = 0;
#pragma unroll
    for (int c = 0; c < NCH; c++) {
        const int cnt = g_cnt[col * NCH + c];
        const unsigned short* src = g_idx + ((size_t)col * NCH + c) * CAPC;
        for (int j = 0; j < cnt; j++) {
            if (n < CAP) dst[n] = (unsigned short)(src[j] * WSTRIDE);
            n++;
        }
    }
    g_ccnt[col] = (n < CAP) ? n : CAP;
}

// ---------------------------------------------------------------------------
// SMEM-resident sparse gather:
//   block = (oc, b); stages W1 rows [oc*16 .. oc*16+15] (2312 x 16, stride 17)
//   into shared once, then y1[b, oc*16+l, t] = sum_{i active} W1[oc*16+l, i]
//   served entirely from LDS. Warp halves process even/odd list entries.
// ---------------------------------------------------------------------------
#define GTH 384
__global__ __launch_bounds__(GTH) void gather_kernel(const float* __restrict__ W1) {
    extern __shared__ float sm[];
    float* ws    = sm;                                // (2312+1)*17 floats
    float* otile = sm + OT_OFF;                       // 16*350 floats
    unsigned short* ist = (unsigned short*)(sm + IST_OFF); // 16B-aligned

    const int oc    = blockIdx.x;        // 0..31
    const int b     = blockIdx.y;        // 0..31
    const int obase = oc * 16;
    const int tid   = threadIdx.x;

    // stage W slice: ws[i*17 + l] = W1[(obase+l)*NIN + i], coalesced over i
#pragma unroll
    for (int l = 0; l < 16; l++) {
        const float* __restrict__ src = W1 + (size_t)(obase + l) * NIN;
        for (int i = tid; i < NIN; i += GTH) ws[i * WSTRIDE + l] = src[i];
    }
    if (tid < WSTRIDE) ws[(size_t)NIN * WSTRIDE + tid] = 0.0f;  // dummy zero row
    __syncthreads();

    const int warp = tid >> 5;
    const int lane = tid & 31;
    const int half = lane >> 4;
    const int l    = lane & 15;
    unsigned short* st0 = ist + warp * 192;     // [0..95] even entries, [96..191] odd
    const float* __restrict__ wl = ws + l;

    for (int t = warp; t < T_; t += 12) {
        const int col = b * T_ + t;
        const int n   = g_ccnt[col];
        const int m   = (n + 7) & ~7;
        const unsigned short* __restrict__ gsrc = g_cidx + (size_t)col * CAP;
        for (int j = lane; j < m; j += 32) {
            unsigned short v = (j < n) ? gsrc[j] : (unsigned short)DUMMYV;
            if (j & 1) st0[96 + (j >> 1)] = v;
            else       st0[(j >> 1)]      = v;
        }
        __syncwarp();

        const unsigned short* myidx = st0 + (half ? 96 : 0);
        const int mp = m >> 1;                  // multiple of 4
        float a0 = 0.f, a1 = 0.f, a2 = 0.f, a3 = 0.f;
        for (int j = 0; j < mp; j += 4) {
            ushort4 iv = *(const ushort4*)(myidx + j);
            a0 += wl[iv.x];
            a1 += wl[iv.y];
            a2 += wl[iv.z];
            a3 += wl[iv.w];
        }
        float acc = (a0 + a1) + (a2 + a3);
        acc += __shfl_xor_sync(0xffffffffu, acc, 16);
        if (!half) otile[l * T_ + t] = acc;
        __syncwarp();
    }
    __syncthreads();

    // coalesced store of the [16 x 350] output tile
    for (int idx = tid; idx < 16 * T_; idx += GTH) {
        const int lo = idx / T_;
        const int tt = idx - lo * T_;
        g_y1[((size_t)b * NHID + obase + lo) * T_ + tt] = otile[idx];
    }
}

// ---------------------------------------------------------------------------
// Fused psp-IIR (+exact TK truncation correction via SMEM ring) + spike scan.
// One thread per (b,channel) row; rings in shared (stride 101 -> no conflicts).
// ---------------------------------------------------------------------------
#define TSTEP 32
#define RSTR  101
__global__ __launch_bounds__(128) void iir_scan_kernel(
    const float* __restrict__ Y, float* __restrict__ Sout, int nrows)
{
    extern __shared__ float sm[];
    float* ringP = sm;                       // 128*101
    float* ringS = sm + 128 * RSTR;          // 128*101
    float* yt    = sm + 2 * 128 * RSTR;      // 128*33
    float* stl   = yt + 128 * 33;            // 128*33

    const int tid  = threadIdx.x;
    const int lane = tid & 31;
    const int warp = tid >> 5;
    const int row0 = blockIdx.x * 128;

    for (int k = tid; k < 128 * RSTR; k += 128) { ringP[k] = 0.0f; ringS[k] = 0.0f; }
    __syncthreads();

    float P = 0.0f, S = 0.0f;     // psp states
    float a = 0.0f, bst = 0.0f;   // refractory states
    int   rp = 0;
    const int rbase = tid * RSTR;

    for (int t0 = 0; t0 < T_; t0 += TSTEP) {
        const int steps = (T_ - t0 < TSTEP) ? (T_ - t0) : TSTEP;

        // coalesced stage-in
#pragma unroll 8
        for (int j = 0; j < 32; j++) {
            const int r  = j * 4 + warp;
            const int gr = row0 + r;
            const int t  = t0 + lane;
            float v = 0.0f;
            if (gr < nrows && t < T_) v = Y[(size_t)gr * T_ + t];
            yt[r * 33 + lane] = v;
        }
        __syncthreads();

        for (int k = 0; k < steps; k++) {
            const float Pold = ringP[rbase + rp];
            const float Sold = ringS[rbase + rp];
            const float corr = fmaf(-K2C, Sold, -K3C * Pold);
            const float yv   = yt[tid * 33 + k];

            const float dP = D_SR * P;
            S = fmaf(D_SR, S, dP);
            P = dP + yv;
            ringP[rbase + rp] = P;
            ringS[rbase + rp] = S;
            rp = (rp == TK - 1) ? 0 : rp + 1;

            const float u = fmaf(C_E, S, fmaf(C_REF, bst, corr));
            const float s = (u >= THETA) ? 1.0f : 0.0f;
            const float g = D_REF * a;
            bst = fmaf(D_REF, bst, g);
            a   = g + s;
            stl[tid * 33 + k] = s;
        }
        __syncthreads();

        // coalesced stage-out
#pragma unroll 8
        for (int j = 0; j < 32; j++) {
            const int r  = j * 4 + warp;
            const int gr = row0 + r;
            const int t  = t0 + lane;
            if (gr < nrows && t < T_)
                Sout[(size_t)gr * T_ + t] = stl[r * 33 + lane];
        }
        __syncthreads();
    }
}

// ---------------------------------------------------------------------------
// GEMM2: z[b,j,t] = sum_o W2[j,o] * s1[b,o,t]
// ---------------------------------------------------------------------------
__global__ __launch_bounds__(320) void gemm2_kernel(
    const float* __restrict__ W2, const float* __restrict__ S1,
    float* __restrict__ Z)
{
    const int b  = blockIdx.y;
    const int j  = threadIdx.x >> 5;
    const int tl = threadIdx.x & 31;
    const int t  = blockIdx.x * 32 + tl;

    __shared__ float w2s[NOUT * NHID];
    for (int i = threadIdx.x; i < NOUT * NHID; i += 320) w2s[i] = W2[i];
    __syncthreads();

    if (t >= T_) return;

    const float* __restrict__ s = S1 + (size_t)b * NHID * T_ + t;
    const float* __restrict__ w = w2s + j * NHID;
    float acc = 0.0f;
#pragma unroll 8
    for (int o = 0; o < NHID; o++)
        acc += w[o] * s[(size_t)o * T_];

    Z[((size_t)b * NOUT + j) * T_ + t] = acc;
}

// ---------------------------------------------------------------------------
extern "C" void kernel_launch(void* const* d_in, const int* in_sizes, int n_in,
                              void* d_out, int out_size)
{
    const float* spikeInput = (const float*)d_in[0];  // [32, 2312, 350]
    const float* W1         = (const float*)d_in[1];  // [512, 2312]
    const float* W2         = (const float*)d_in[2];  // [10, 512]
    float*       out        = (float*)d_out;          // [32, 10, 350]

    float *y1p, *s1p, *z2p;
    cudaGetSymbolAddress((void**)&y1p, g_y1);
    cudaGetSymbolAddress((void**)&s1p, g_s1);
    cudaGetSymbolAddress((void**)&z2p, g_z2);

    const int gather_smem = (int)(GATHER_SMEM_FLOATS * sizeof(float));              // ~184.5 KB
    const int scan_smem   = (int)((2 * 128 * RSTR + 2 * 128 * 33) * sizeof(float)); // ~137.2 KB

    cudaFuncSetAttribute(gather_kernel,   cudaFuncAttributeMaxDynamicSharedMemorySize, gather_smem);
    cudaFuncSetAttribute(iir_scan_kernel, cudaFuncAttributeMaxDynamicSharedMemorySize, scan_smem);

    dim3 gb((T_ + 127) / 128, NCH, B_);            // (3, 8, 32)
    build_idx_kernel<<<gb, 128>>>(spikeInput);

    compact_idx_kernel<<<(NCOL + 127) / 128, 128>>>();

    dim3 gg(NHID / 16, B_);                        // (32, 32)
    gather_kernel<<<gg, GTH, gather_smem>>>(W1);

    iir_scan_kernel<<<(B_ * NHID + 127) / 128, 128, scan_smem>>>(y1p, s1p, B_ * NHID);

    dim3 g2((T_ + 31) / 32, B_);                   // (11, 32)
    gemm2_kernel<<<g2, 320>>>(W2, s1p, z2p);

    iir_scan_kernel<<<(B_ * NOUT + 127) / 128, 128, scan_smem>>>(z2p, out, B_ * NOUT);
}

// round 7
// speedup vs baseline: 1.7222x; 1.7222x over previous
#include <cuda_runtime.h>
#include <math.h>

#define B_    32
#define NIN   2312
#define NHID  512
#define NOUT  10
#define T_    350
#define TK    100
#define THETA 10.0f

// refractory IIR constants
#define D_REF 0.36787944117144233f
#define C_REF (-5.43656365691809f)

// psp alpha-kernel IIR constants: eps[k] = (e/10) * k * d^k, d = e^{-0.1}
#define D_SR  0.90483741803595952f    // exp(-0.1)
#define C_E   0.27182818284590452f    // e/10
#define K2C   1.2340980408667956e-05f // C_E * exp(-10)
#define K3C   1.2340980408667956e-03f // 100 * C_E * exp(-10)

// sparse index structure: per (b,t) column, NCH chunks of the input dim
#define NCH   8
#define CHUNK 289
#define CAPC  96
#define NCOL  (B_ * T_)           // 11200

// scan tiling: 350 = 7 * 50; history 100 = exactly 2 chunks back
#define TSTEP 50
#define TPAD  51                  // odd stride -> bank-conflict-free

// ------------------------- static device scratch ---------------------------
__device__ float g_W1T[(size_t)NIN * NHID];                    // [i, o]
__device__ unsigned short g_idx[(size_t)NCOL * NCH * CAPC];
__device__ int            g_cnt[(size_t)NCOL * NCH];
__device__ float g_y1[(size_t)B_ * NHID * T_];
__device__ float g_s1[(size_t)B_ * NHID * T_];
__device__ float g_z2[(size_t)B_ * NOUT * T_];

// ---------------------------------------------------------------------------
// Tiled transpose: W1T[i*512 + o] = W1[o*2312 + i]
// ---------------------------------------------------------------------------
__global__ __launch_bounds__(256) void transpose_w1_kernel(const float* __restrict__ W1) {
    __shared__ float tile[32][33];
    const int i0 = blockIdx.x * 32;
    const int o0 = blockIdx.y * 32;
    const int lx = threadIdx.x & 31;
    const int ly = threadIdx.x >> 5;

#pragma unroll
    for (int r = 0; r < 32; r += 8) {
        int o = o0 + ly + r;
        int i = i0 + lx;
        tile[ly + r][lx] = (i < NIN) ? W1[(size_t)o * NIN + i] : 0.0f;
    }
    __syncthreads();
#pragma unroll
    for (int r = 0; r < 32; r += 8) {
        int i = i0 + ly + r;
        int o = o0 + lx;
        if (i < NIN) g_W1T[(size_t)i * NHID + o] = tile[lx][ly + r];
    }
}

// ---------------------------------------------------------------------------
// Build per-(b,t,chunk) lists of active input indices (coalesced over t).
// ---------------------------------------------------------------------------
__global__ __launch_bounds__(128) void build_idx_kernel(const float* __restrict__ X) {
    const int t = blockIdx.x * 128 + threadIdx.x;
    const int c = blockIdx.y;
    const int b = blockIdx.z;
    if (t >= T_) return;

    const int col = b * T_ + t;
    unsigned short* dst = g_idx + ((size_t)col * NCH + c) * CAPC;
    const float* __restrict__ xb = X + (size_t)b * NIN * T_ + t;

    int cnt = 0;
    const int i0 = c * CHUNK;
#pragma unroll 4
    for (int i = i0; i < i0 + CHUNK; i++) {
        float v = xb[(size_t)i * T_];
        if (v != 0.0f) {
            if (cnt < CAPC) dst[cnt] = (unsigned short)i;
            cnt++;
        }
    }
    g_cnt[col * NCH + c] = (cnt < CAPC) ? cnt : CAPC;
}

// ---------------------------------------------------------------------------
// Sparse gather-accumulate (R3, proven at LTS roofline):
//   y1[b,:,t] = sum_{i active(b,t)} W1T[i,:]
// One block per (b,t) column; 128 threads x float4 = 512 outputs.
// ---------------------------------------------------------------------------
__global__ __launch_bounds__(128) void sparse_accum_kernel() {
    const int col = blockIdx.x;
    const int tid = threadIdx.x;

    __shared__ unsigned short sidx[NCH * CAPC];
    __shared__ int psum[NCH + 1];

    if (tid == 0) {
        int s = 0;
        psum[0] = 0;
#pragma unroll
        for (int c = 0; c < NCH; c++) { s += g_cnt[col * NCH + c]; psum[c + 1] = s; }
    }
    __syncthreads();

    if (tid < NCH) {
        const int c = tid;
        const int n = psum[c + 1] - psum[c];
        const unsigned short* src = g_idx + ((size_t)col * NCH + c) * CAPC;
        unsigned short* d = sidx + psum[c];
        for (int k = 0; k < n; k++) d[k] = src[k];
    }
    __syncthreads();

    const int tot = psum[NCH];
    const float4* __restrict__ W = (const float4*)g_W1T;

    float4 acc = make_float4(0.f, 0.f, 0.f, 0.f);
    int k = 0;
    for (; k + 4 <= tot; k += 4) {
        int i0 = sidx[k], i1 = sidx[k + 1], i2 = sidx[k + 2], i3 = sidx[k + 3];
        float4 w0 = W[(size_t)i0 * 128 + tid];
        float4 w1 = W[(size_t)i1 * 128 + tid];
        float4 w2 = W[(size_t)i2 * 128 + tid];
        float4 w3 = W[(size_t)i3 * 128 + tid];
        acc.x += w0.x; acc.y += w0.y; acc.z += w0.z; acc.w += w0.w;
        acc.x += w1.x; acc.y += w1.y; acc.z += w1.z; acc.w += w1.w;
        acc.x += w2.x; acc.y += w2.y; acc.z += w2.z; acc.w += w2.w;
        acc.x += w3.x; acc.y += w3.y; acc.z += w3.z; acc.w += w3.w;
    }
    for (; k < tot; k++) {
        float4 w0 = W[(size_t)sidx[k] * 128 + tid];
        acc.x += w0.x; acc.y += w0.y; acc.z += w0.z; acc.w += w0.w;
    }

    const int b = col / T_;
    const int t = col - b * T_;
    float* dst = g_y1 + ((size_t)b * NHID + tid * 4) * T_ + t;
    dst[0]      = acc.x;
    dst[T_]     = acc.y;
    dst[2 * T_] = acc.z;
    dst[3 * T_] = acc.w;
}

// ---------------------------------------------------------------------------
// Scan v3: fused psp-IIR + exact TK=100 truncation correction via a SECOND
// IIR fed by y[t-100] (bitwise-identical to storing delayed states), plus
// threshold/refractory dynamics. One thread per row. No state ring: with
// TSTEP=50, y[t-100] sits exactly 2 chunks back in a 3-deep rotating y tile.
// ---------------------------------------------------------------------------
__global__ __launch_bounds__(128) void iir_scan_kernel(
    const float* __restrict__ Y, float* __restrict__ Sout, int nrows)
{
    extern __shared__ float sm[];
    // layout: ybuf[3][128*TPAD], sbuf[128*TPAD]
    float* ybuf0 = sm;
    float* ybuf1 = sm + 128 * TPAD;
    float* ybuf2 = sm + 2 * 128 * TPAD;
    float* sbuf  = sm + 3 * 128 * TPAD;
    float* ybufs[3] = {ybuf0, ybuf1, ybuf2};

    const int tid  = threadIdx.x;
    const int row0 = blockIdx.x * 128;

    float P = 0.f, S = 0.f;       // psp states (current)
    float P2 = 0.f, S2 = 0.f;     // psp states on 100-delayed input
    float a = 0.f, bst = 0.f;     // refractory states

    for (int c = 0; c < 7; c++) {
        float* ycur = ybufs[c % 3];

        // stage-in chunk c (rows x 50, coalesced in 50-float runs)
        for (int e = tid; e < 128 * TSTEP; e += 128) {
            const int r = e / TSTEP;
            const int k = e - r * TSTEP;
            const int gr = row0 + r;
            float v = 0.0f;
            if (gr < nrows) v = Y[(size_t)gr * T_ + c * TSTEP + k];
            ycur[r * TPAD + k] = v;
        }
        __syncthreads();

        const float* yc = ycur + tid * TPAD;
        const float* yo = (c >= 2) ? (ybufs[(c + 1) % 3] + tid * TPAD) : 0;  // chunk c-2
        float* sb = sbuf + tid * TPAD;

#pragma unroll 2
        for (int k = 0; k < TSTEP; k++) {
            const float yv   = yc[k];
            const float yold = (c >= 2) ? yo[k] : 0.0f;

            // delayed psp IIR (gives P(t-100), S(t-100) bit-exactly)
            const float dP2 = D_SR * P2;
            S2 = fmaf(D_SR, S2, dP2);
            P2 = dP2 + yold;
            const float corr = fmaf(-K2C, S2, -K3C * P2);

            // main psp IIR
            const float dP = D_SR * P;
            S = fmaf(D_SR, S, dP);
            P = dP + yv;

            // membrane + refractory
            const float u = fmaf(C_E, S, fmaf(C_REF, bst, corr));
            const float s = (u >= THETA) ? 1.0f : 0.0f;
            const float g = D_REF * a;
            bst = fmaf(D_REF, bst, g);
            a   = g + s;
            sb[k] = s;
        }
        __syncthreads();

        // stage-out spikes for chunk c
        for (int e = tid; e < 128 * TSTEP; e += 128) {
            const int r = e / TSTEP;
            const int k = e - r * TSTEP;
            const int gr = row0 + r;
            if (gr < nrows)
                Sout[(size_t)gr * T_ + c * TSTEP + k] = sbuf[r * TPAD + k];
        }
        __syncthreads();
    }
}

// ---------------------------------------------------------------------------
// GEMM2: z[b,j,t] = sum_o W2[j,o] * s1[b,o,t]
// ---------------------------------------------------------------------------
__global__ __launch_bounds__(320) void gemm2_kernel(
    const float* __restrict__ W2, const float* __restrict__ S1,
    float* __restrict__ Z)
{
    const int b  = blockIdx.y;
    const int j  = threadIdx.x >> 5;
    const int tl = threadIdx.x & 31;
    const int t  = blockIdx.x * 32 + tl;

    __shared__ float w2s[NOUT * NHID];
    for (int i = threadIdx.x; i < NOUT * NHID; i += 320) w2s[i] = W2[i];
    __syncthreads();

    if (t >= T_) return;

    const float* __restrict__ s = S1 + (size_t)b * NHID * T_ + t;
    const float* __restrict__ w = w2s + j * NHID;
    float acc = 0.0f;
#pragma unroll 8
    for (int o = 0; o < NHID; o++)
        acc += w[o] * s[(size_t)o * T_];

    Z[((size_t)b * NOUT + j) * T_ + t] = acc;
}

// ---------------------------------------------------------------------------
extern "C" void kernel_launch(void* const* d_in, const int* in_sizes, int n_in,
                              void* d_out, int out_size)
{
    const float* spikeInput = (const float*)d_in[0];  // [32, 2312, 350]
    const float* W1         = (const float*)d_in[1];  // [512, 2312]
    const float* W2         = (const float*)d_in[2];  // [10, 512]
    float*       out        = (float*)d_out;          // [32, 10, 350]

    float *y1p, *s1p, *z2p;
    cudaGetSymbolAddress((void**)&y1p, g_y1);
    cudaGetSymbolAddress((void**)&s1p, g_s1);
    cudaGetSymbolAddress((void**)&z2p, g_z2);

    const int scan_smem = (int)(4 * 128 * TPAD * sizeof(float));   // ~104.4 KB
    cudaFuncSetAttribute(iir_scan_kernel, cudaFuncAttributeMaxDynamicSharedMemorySize, scan_smem);

    dim3 gt((NIN + 31) / 32, NHID / 32);      // (73, 16)
    transpose_w1_kernel<<<gt, 256>>>(W1);

    dim3 gb((T_ + 127) / 128, NCH, B_);       // (3, 8, 32)
    build_idx_kernel<<<gb, 128>>>(spikeInput);

    sparse_accum_kernel<<<NCOL, 128>>>();

    iir_scan_kernel<<<(B_ * NHID + 127) / 128, 128, scan_smem>>>(y1p, s1p, B_ * NHID);

    dim3 g2((T_ + 31) / 32, B_);              // (11, 32)
    gemm2_kernel<<<g2, 320>>>(W2, s1p, z2p);

    iir_scan_kernel<<<(B_ * NOUT + 127) / 128, 128, scan_smem>>>(z2p, out, B_ * NOUT);
}

// round 8
// speedup vs baseline: 2.6609x; 1.5451x over previous
#include <cuda_runtime.h>
#include <math.h>

#define B_    32
#define NIN   2312
#define NHID  512
#define NOUT  10
#define T_    350
#define TK    100
#define THETA 10.0f

// refractory IIR constants
#define D_REF 0.36787944117144233f
#define C_REF (-5.43656365691809f)

// psp alpha-kernel IIR constants: eps[k] = (e/10) * k * d^k, d = e^{-0.1}
#define D_SR  0.90483741803595952f    // exp(-0.1)
#define C_E   0.27182818284590452f    // e/10
#define K2C   1.2340980408667956e-05f // C_E * exp(-10)
#define K3C   1.2340980408667956e-03f // 100 * C_E * exp(-10)

// sparse index structure
#define NCH   8
#define CHUNK 289
#define CAPC  96
#define NCOL  (B_ * T_)           // 11200

#define R1    (B_ * NHID)         // 16384 layer-1 rows
#define R2    (B_ * NOUT)         // 320   layer-2 rows

// ------------------------- static device scratch ---------------------------
__device__ float g_W1T[(size_t)NIN * NHID];                 // [i, o]
__device__ unsigned short g_idx[(size_t)NCOL * NCH * CAPC];
__device__ int            g_cnt[(size_t)NCOL * NCH];
__device__ float g_y1[(size_t)T_ * R1];   // t-major: [t][b*512+o]
__device__ float g_s1[(size_t)T_ * R1];   // t-major
__device__ float g_z2[(size_t)T_ * R2];   // t-major

// ---------------------------------------------------------------------------
// Tiled transpose: W1T[i*512 + o] = W1[o*2312 + i]
// ---------------------------------------------------------------------------
__global__ __launch_bounds__(256) void transpose_w1_kernel(const float* __restrict__ W1) {
    __shared__ float tile[32][33];
    const int i0 = blockIdx.x * 32;
    const int o0 = blockIdx.y * 32;
    const int lx = threadIdx.x & 31;
    const int ly = threadIdx.x >> 5;

#pragma unroll
    for (int r = 0; r < 32; r += 8) {
        int o = o0 + ly + r;
        int i = i0 + lx;
        tile[ly + r][lx] = (i < NIN) ? W1[(size_t)o * NIN + i] : 0.0f;
    }
    __syncthreads();
#pragma unroll
    for (int r = 0; r < 32; r += 8) {
        int i = i0 + ly + r;
        int o = o0 + lx;
        if (i < NIN) g_W1T[(size_t)i * NHID + o] = tile[lx][ly + r];
    }
}

// ---------------------------------------------------------------------------
// Build per-(b,t,chunk) lists of active input indices (coalesced over t).
// ---------------------------------------------------------------------------
__global__ __launch_bounds__(128) void build_idx_kernel(const float* __restrict__ X) {
    const int t = blockIdx.x * 128 + threadIdx.x;
    const int c = blockIdx.y;
    const int b = blockIdx.z;
    if (t >= T_) return;

    const int col = b * T_ + t;
    unsigned short* dst = g_idx + ((size_t)col * NCH + c) * CAPC;
    const float* __restrict__ xb = X + (size_t)b * NIN * T_ + t;

    int cnt = 0;
    const int i0 = c * CHUNK;
#pragma unroll 4
    for (int i = i0; i < i0 + CHUNK; i++) {
        float v = xb[(size_t)i * T_];
        if (v != 0.0f) {
            if (cnt < CAPC) dst[cnt] = (unsigned short)i;
            cnt++;
        }
    }
    g_cnt[col * NCH + c] = (cnt < CAPC) ? cnt : CAPC;
}

// ---------------------------------------------------------------------------
// Sparse gather-accumulate (proven at LTS roofline), now with one fully
// coalesced float4 store into the t-major y1 tensor.
//   y1T[t][b*512 + :] = sum_{i active(b,t)} W1T[i,:]
// ---------------------------------------------------------------------------
__global__ __launch_bounds__(128) void sparse_accum_kernel() {
    const int col = blockIdx.x;
    const int tid = threadIdx.x;

    __shared__ unsigned short sidx[NCH * CAPC];
    __shared__ int psum[NCH + 1];

    if (tid == 0) {
        int s = 0;
        psum[0] = 0;
#pragma unroll
        for (int c = 0; c < NCH; c++) { s += g_cnt[col * NCH + c]; psum[c + 1] = s; }
    }
    __syncthreads();

    if (tid < NCH) {
        const int c = tid;
        const int n = psum[c + 1] - psum[c];
        const unsigned short* src = g_idx + ((size_t)col * NCH + c) * CAPC;
        unsigned short* d = sidx + psum[c];
        for (int k = 0; k < n; k++) d[k] = src[k];
    }
    __syncthreads();

    const int tot = psum[NCH];
    const float4* __restrict__ W = (const float4*)g_W1T;

    float4 acc = make_float4(0.f, 0.f, 0.f, 0.f);
    int k = 0;
    for (; k + 4 <= tot; k += 4) {
        int i0 = sidx[k], i1 = sidx[k + 1], i2 = sidx[k + 2], i3 = sidx[k + 3];
        float4 w0 = W[(size_t)i0 * 128 + tid];
        float4 w1 = W[(size_t)i1 * 128 + tid];
        float4 w2 = W[(size_t)i2 * 128 + tid];
        float4 w3 = W[(size_t)i3 * 128 + tid];
        acc.x += w0.x; acc.y += w0.y; acc.z += w0.z; acc.w += w0.w;
        acc.x += w1.x; acc.y += w1.y; acc.z += w1.z; acc.w += w1.w;
        acc.x += w2.x; acc.y += w2.y; acc.z += w2.z; acc.w += w2.w;
        acc.x += w3.x; acc.y += w3.y; acc.z += w3.z; acc.w += w3.w;
    }
    for (; k < tot; k++) {
        float4 w0 = W[(size_t)sidx[k] * 128 + tid];
        acc.x += w0.x; acc.y += w0.y; acc.z += w0.z; acc.w += w0.w;
    }

    const int b = col / T_;
    const int t = col - b * T_;
    float4* dst = (float4*)(g_y1 + (size_t)t * R1 + b * NHID);
    dst[tid] = acc;   // 128 lanes x float4 = 2KB fully coalesced
}

// ---------------------------------------------------------------------------
// Scan v4: t-major, no smem, register-prefetched (10-deep) LDGs.
// Fused psp-IIR + exact TK=100 truncation correction via a second IIR fed by
// y[t-100] (direct pointer 100 t-slices back) + threshold/refractory scan.
// One thread per row. tmajor_out: 1 -> Sout[t*stride+row]; 0 -> Sout[row*T_+t].
// ---------------------------------------------------------------------------
__global__ __launch_bounds__(128) void iir_scan_kernel(
    const float* __restrict__ Y, float* __restrict__ Sout,
    int stride, int nrows, int tmajor_out)
{
    const int row = blockIdx.x * 128 + threadIdx.x;
    const bool ok = (row < nrows);

    const float* __restrict__ yp = Y + row;

    float P = 0.f, S = 0.f;       // psp states
    float P2 = 0.f, S2 = 0.f;     // psp states on 100-delayed input
    float a = 0.f, bst = 0.f;     // refractory states

    for (int c = 0; c < 35; c++) {
        const int t0 = c * 10;
        float yv[10], yo[10], sb[10];

#pragma unroll
        for (int k = 0; k < 10; k++)
            yv[k] = ok ? yp[(size_t)(t0 + k) * stride] : 0.0f;
        if (c >= 10) {
#pragma unroll
            for (int k = 0; k < 10; k++)
                yo[k] = ok ? yp[(size_t)(t0 + k - TK) * stride] : 0.0f;
        } else {
#pragma unroll
            for (int k = 0; k < 10; k++) yo[k] = 0.0f;
        }

#pragma unroll
        for (int k = 0; k < 10; k++) {
            // delayed psp IIR -> bit-exact P(t-100), S(t-100)
            const float dP2 = D_SR * P2;
            S2 = fmaf(D_SR, S2, dP2);
            P2 = dP2 + yo[k];
            const float corr = fmaf(-K2C, S2, -K3C * P2);

            // main psp IIR
            const float dP = D_SR * P;
            S = fmaf(D_SR, S, dP);
            P = dP + yv[k];

            // membrane + refractory
            const float u = fmaf(C_E, S, fmaf(C_REF, bst, corr));
            const float s = (u >= THETA) ? 1.0f : 0.0f;
            const float g = D_REF * a;
            bst = fmaf(D_REF, bst, g);
            a   = g + s;
            sb[k] = s;
        }

        if (ok) {
            if (tmajor_out) {
#pragma unroll
                for (int k = 0; k < 10; k++)
                    Sout[(size_t)(t0 + k) * stride + row] = sb[k];
            } else {
#pragma unroll
                for (int k = 0; k < 10; k++)
                    Sout[(size_t)row * T_ + t0 + k] = sb[k];
            }
        }
    }
}

// ---------------------------------------------------------------------------
// GEMM2 on t-major s1: warp per (b,t) column.
//   z2T[t][b*10+j] = sum_o W2[j,o] * s1T[t][b*512+o]
// ---------------------------------------------------------------------------
__global__ __launch_bounds__(256) void gemm2_kernel(
    const float* __restrict__ W2, const float* __restrict__ S1T,
    float* __restrict__ Z2T)
{
    __shared__ float w2s[NOUT * NHID];   // 20 KB
    for (int i = threadIdx.x; i < NOUT * NHID; i += 256) w2s[i] = W2[i];
    __syncthreads();

    const int warp = threadIdx.x >> 5;
    const int lane = threadIdx.x & 31;
    const int col  = blockIdx.x * 8 + warp;   // 0..11199
    const int b    = col / T_;
    const int t    = col - b * T_;

    const float4* __restrict__ sv = (const float4*)(S1T + (size_t)t * R1 + b * NHID);
    const float4* __restrict__ wv = (const float4*)w2s;

    float acc[NOUT];
#pragma unroll
    for (int j = 0; j < NOUT; j++) acc[j] = 0.0f;

#pragma unroll
    for (int p = 0; p < 4; p++) {
        float4 v = sv[p * 32 + lane];
#pragma unroll
        for (int j = 0; j < NOUT; j++) {
            float4 w = wv[j * 128 + p * 32 + lane];
            acc[j] += w.x * v.x + w.y * v.y + w.z * v.z + w.w * v.w;
        }
    }

#pragma unroll
    for (int j = 0; j < NOUT; j++) {
#pragma unroll
        for (int sh = 16; sh > 0; sh >>= 1)
            acc[j] += __shfl_xor_sync(0xffffffffu, acc[j], sh);
    }

    if (lane < NOUT)
        Z2T[(size_t)t * R2 + b * NOUT + lane] = acc[lane];
}

// ---------------------------------------------------------------------------
extern "C" void kernel_launch(void* const* d_in, const int* in_sizes, int n_in,
                              void* d_out, int out_size)
{
    const float* spikeInput = (const float*)d_in[0];  // [32, 2312, 350]
    const float* W1         = (const float*)d_in[1];  // [512, 2312]
    const float* W2         = (const float*)d_in[2];  // [10, 512]
    float*       out        = (float*)d_out;          // [32, 10, 350]

    float *y1p, *s1p, *z2p;
    cudaGetSymbolAddress((void**)&y1p, g_y1);
    cudaGetSymbolAddress((void**)&s1p, g_s1);
    cudaGetSymbolAddress((void**)&z2p, g_z2);

    dim3 gt((NIN + 31) / 32, NHID / 32);      // (73, 16)
    transpose_w1_kernel<<<gt, 256>>>(W1);

    dim3 gb((T_ + 127) / 128, NCH, B_);       // (3, 8, 32)
    build_idx_kernel<<<gb, 128>>>(spikeInput);

    sparse_accum_kernel<<<NCOL, 128>>>();

    iir_scan_kernel<<<R1 / 128, 128>>>(y1p, s1p, R1, R1, 1);

    gemm2_kernel<<<NCOL / 8, 256>>>(W2, s1p, z2p);

    iir_scan_kernel<<<(R2 + 127) / 128, 128>>>(z2p, out, R2, R2, 0);
}